// round 8
// baseline (speedup 1.0000x reference)
#include <cuda_runtime.h>

// Problem constants (fixed by the reference):
//   S=3 symmetries, B=512 batches, N=1000 points, G=32 (G^3=32768 voxels)
//   GRID_MIN = -0.5 + 0.5/32 = -0.484375, scale = GRID/(2*GBOUND) = 32
#define S_SYM   3
#define B_BATCH 512
#define N_PTS   1000
#define G3      32768
#define SB_TOT  (S_SYM * B_BATCH)
#define GRID_MIN_F (-0.484375f)
#define NTHREADS 1024
#define NWARPS   (NTHREADS / 32)
#define NEDGE    384     // 3 axes * 4 clamp combos * 32 positions

// Per-batch partial sums: [0..511]=plane, [512..1023]=quat. Plus ticket.
__device__ float g_partial[2 * B_BATCH];
__device__ unsigned int g_count;   // zero-initialized; reset by last block

__device__ __forceinline__ float fast_sqrt(float x) {
    float r;
    asm("sqrt.approx.f32 %0, %1;" : "=f"(r) : "f"(x));
    return r;
}
__device__ __forceinline__ float fast_rcp(float x) {
    float r;
    asm("rcp.approx.f32 %0, %1;" : "=f"(r) : "f"(x));
    return r;
}

__global__ __launch_bounds__(NTHREADS, 1)
void sym_loss_kernel(const float* __restrict__ planes,
                     const float* __restrict__ quats,
                     const float* __restrict__ cps,
                     const float* __restrict__ pts,
                     const float* __restrict__ vol,
                     float* __restrict__ out)
{
    __shared__ float4 s_edge[NEDGE];           // {cp0,cp1,cp2,vol} of edge voxels
    __shared__ float  s_red[2 * NWARPS];
    __shared__ int    s_is_last;

    const int b = blockIdx.x;                  // one block per batch
    const float* cpb = cps + (size_t)b * (3 * G3);
    const float* vb  = vol + (size_t)b * G3;
    const float* pb  = pts + (size_t)b * (3 * N_PTS);

    // Stage the 384 edge voxels (>=2 coords clamped to 0/31).
    // Layout: axis = i/128 (the FREE axis), combo = (i%128)/32, pos = i%32.
    if (threadIdx.x < NEDGE) {
        int i = threadIdx.x;
        int axis  = i >> 7;
        int combo = (i >> 5) & 3;
        int pos   = i & 31;
        int hi0 = (combo >> 1) * 31;
        int hi1 = (combo & 1) * 31;
        int ix, iy, iz;
        if (axis == 0)      { ix = pos; iy = hi0; iz = hi1; }
        else if (axis == 1) { ix = hi0; iy = pos; iz = hi1; }
        else                { ix = hi0; iy = hi1; iz = pos; }
        int lin = ix * 1024 + iy * 32 + iz;
        const float* c = cpb + 3 * lin;
        s_edge[i] = make_float4(__ldg(c), __ldg(c + 1), __ldg(c + 2), __ldg(vb + lin));
    }
    __syncthreads();

    float lp = 0.0f, lq = 0.0f;

    const int n = threadIdx.x;                 // one point per thread
    if (n < N_PTS) {
        const float px = pb[3 * n + 0];
        const float py = pb[3 * n + 1];
        const float pz = pb[3 * n + 2];

        float tx[6], ty[6], tz[6];
        #pragma unroll
        for (int s = 0; s < S_SYM; s++) {
            float4 pl = reinterpret_cast<const float4*>(planes)[s * B_BATCH + b];
            float4 qq = reinterpret_cast<const float4*>(quats)[s * B_BATCH + b];
            float inv = fast_rcp(pl.x * pl.x + pl.y * pl.y + pl.z * pl.z + 1e-8f);
            // plane reflection
            float t = 2.0f * (px * pl.x + py * pl.y + pz * pl.z + pl.w) * inv;
            tx[2 * s] = px - t * pl.x;
            ty[2 * s] = py - t * pl.y;
            tz[2 * s] = pz - t * pl.z;
            // quat rotation (w,x,y,z) = (qq.x, qq.y, qq.z, qq.w), unnormalized
            float qw = qq.x, qx = qq.y, qy = qq.z, qz = qq.w;
            float tw = -qx * px - qy * py - qz * pz;
            float ax =  qw * px + qy * pz - qz * py;
            float ay =  qw * py - qx * pz + qz * px;
            float az =  qw * pz + qx * py - qy * px;
            tx[2 * s + 1] = -tw * qx + ax * qw - ay * qz + az * qy;
            ty[2 * s + 1] = -tw * qy + ax * qz + ay * qw - az * qx;
            tz[2 * s + 1] = -tw * qz - ax * qy + ay * qx + az * qw;
        }

        int lin[6], eidx[6];
        bool edge[6];
        #pragma unroll
        for (int j = 0; j < 6; j++) {
            // vx = round(clip((p-GRID_MIN)*32, 0, 31)), round-half-even == jnp.round
            float vx = fminf(fmaxf((tx[j] - GRID_MIN_F) * 32.0f, 0.0f), 31.0f);
            float vy = fminf(fmaxf((ty[j] - GRID_MIN_F) * 32.0f, 0.0f), 31.0f);
            float vz = fminf(fmaxf((tz[j] - GRID_MIN_F) * 32.0f, 0.0f), 31.0f);
            int ix = __float2int_rn(vx);
            int iy = __float2int_rn(vy);
            int iz = __float2int_rn(vz);
            lin[j] = ix * 1024 + iy * 32 + iz;
            bool cx = (ix * (31 - ix) == 0);
            bool cy = (iy * (31 - iy) == 0);
            bool cz = (iz * (31 - iz) == 0);
            edge[j] = ((int)cx + (int)cy + (int)cz) >= 2;
            int idx;
            if (!cx)      idx =       ((iy >> 4) * 2 + (iz >> 4)) * 32 + ix;
            else if (!cy) idx = 128 + ((ix >> 4) * 2 + (iz >> 4)) * 32 + iy;
            else          idx = 256 + ((ix >> 4) * 2 + (iy >> 4)) * 32 + iz;
            eidx[j] = idx;
        }

        // Gather: edge/corner voxels from smem (no LDG), others from global.
        float vm[6], c0[6], c1[6], c2[6];
        #pragma unroll
        for (int j = 0; j < 6; j++) {
            if (edge[j]) {
                float4 cc = s_edge[eidx[j]];
                c0[j] = cc.x; c1[j] = cc.y; c2[j] = cc.z; vm[j] = cc.w;
            } else {
                const float* c = cpb + 3 * lin[j];
                vm[j] = __ldg(vb + lin[j]);
                c0[j] = __ldg(c + 0);
                c1[j] = __ldg(c + 1);
                c2[j] = __ldg(c + 2);
            }
        }

        #pragma unroll
        for (int j = 0; j < 6; j++) {
            float m  = 1.0f - vm[j];
            float dx = (tx[j] - c0[j]) * m;
            float dy = (ty[j] - c1[j]) * m;
            float dz = (tz[j] - c2[j]) * m;
            float r  = fast_sqrt(fmaxf(dx * dx + dy * dy + dz * dz, 1e-30f));
            if (j & 1) lq += r; else lp += r;
        }
    }

    // Deterministic block reduction: warp shuffle then fixed-order smem sum.
    #pragma unroll
    for (int off = 16; off > 0; off >>= 1) {
        lp += __shfl_down_sync(0xffffffffu, lp, off);
        lq += __shfl_down_sync(0xffffffffu, lq, off);
    }
    const int lane = threadIdx.x & 31;
    const int wid  = threadIdx.x >> 5;
    if (lane == 0) { s_red[wid] = lp; s_red[NWARPS + wid] = lq; }
    __syncthreads();
    if (threadIdx.x == 0) {
        float a = 0.0f, c2s = 0.0f;
        #pragma unroll
        for (int i = 0; i < NWARPS; i++) { a += s_red[i]; c2s += s_red[NWARPS + i]; }
        g_partial[b] = a;
        g_partial[B_BATCH + b] = c2s;
        __threadfence();
        unsigned t = atomicAdd(&g_count, 1u);
        s_is_last = (t == B_BATCH - 1);
    }
    __syncthreads();

    // Last block performs the final reduction in a FIXED order (deterministic
    // regardless of which block finishes last).
    if (s_is_last) {
        float a = 0.0f, c2s = 0.0f;
        for (int i = threadIdx.x; i < B_BATCH; i += NTHREADS) {
            a   += g_partial[i];
            c2s += g_partial[B_BATCH + i];
        }
        #pragma unroll
        for (int off = 16; off > 0; off >>= 1) {
            a   += __shfl_down_sync(0xffffffffu, a,   off);
            c2s += __shfl_down_sync(0xffffffffu, c2s, off);
        }
        if (lane == 0) { s_red[wid] = a; s_red[NWARPS + wid] = c2s; }
        __syncthreads();
        if (threadIdx.x == 0) {
            float sa = 0.0f, sc = 0.0f;
            #pragma unroll
            for (int i = 0; i < NWARPS; i++) { sa += s_red[i]; sc += s_red[NWARPS + i]; }
            out[0] = sa * (1.0f / (float)SB_TOT);
            out[1] = sc * (1.0f / (float)SB_TOT);
            g_count = 0;   // reset for next graph replay
        }
    }
}

extern "C" void kernel_launch(void* const* d_in, const int* in_sizes, int n_in,
                              void* d_out, int out_size)
{
    const float* planes = (const float*)d_in[0];  // (3,512,4)
    const float* quats  = (const float*)d_in[1];  // (3,512,4)
    const float* cps    = (const float*)d_in[2];  // (512, 32768*3)
    const float* pts    = (const float*)d_in[3];  // (512,1000,3)
    const float* vol    = (const float*)d_in[4];  // (512,1,32,32,32)
    float* out = (float*)d_out;                   // [lp_mean, lq_mean]

    sym_loss_kernel<<<B_BATCH, NTHREADS>>>(planes, quats, cps, pts, vol, out);
}

// round 9
// speedup vs baseline: 1.2640x; 1.2640x over previous
#include <cuda_runtime.h>

// Problem constants (fixed by the reference):
//   S=3 symmetries, B=512 batches, N=1000 points, G=32 (G^3=32768 voxels)
//   GRID_MIN = -0.5 + 0.5/32 = -0.484375, scale = GRID/(2*GBOUND) = 32
#define S_SYM   3
#define B_BATCH 512
#define N_PTS   1000
#define G3      32768
#define SB_TOT  (S_SYM * B_BATCH)
#define GRID_MIN_F (-0.484375f)
#define NTHREADS 512
#define NWARPS   (NTHREADS / 32)
#define NEDGE    384     // 3 axes * 4 clamp combos * 32 positions

// Per-batch partial sums: [0..511]=plane, [512..1023]=quat. Plus ticket.
__device__ float g_partial[2 * B_BATCH];
__device__ unsigned int g_count;   // zero-initialized; reset by last block

__device__ __forceinline__ float fast_sqrt(float x) {
    float r;
    asm("sqrt.approx.f32 %0, %1;" : "=f"(r) : "f"(x));
    return r;
}
__device__ __forceinline__ float fast_rcp(float x) {
    float r;
    asm("rcp.approx.f32 %0, %1;" : "=f"(r) : "f"(x));
    return r;
}

__global__ __launch_bounds__(NTHREADS, 3)   // cap ~42 regs -> 1536 thr/SM
void sym_loss_kernel(const float* __restrict__ planes,
                     const float* __restrict__ quats,
                     const float* __restrict__ cps,
                     const float* __restrict__ pts,
                     const float* __restrict__ vol,
                     float* __restrict__ out)
{
    __shared__ float4 s_pts[N_PTS];            // padded to 16B for LDS.128
    __shared__ float4 s_edge[NEDGE];           // {cp0,cp1,cp2,vol} of edge voxels
    __shared__ float4 s_sym[2 * S_SYM];        // [0..2]=planes, [3..5]=quats
    __shared__ float  s_red[2 * NWARPS];
    __shared__ int    s_is_last;

    const int b = blockIdx.x;                  // one block per batch
    const float* cpb = cps + (size_t)b * (3 * G3);
    const float* vb  = vol + (size_t)b * G3;
    const float* pb  = pts + (size_t)b * (3 * N_PTS);

    // Stage the 384 edge voxels (>=2 coords clamped to 0/31).
    // Layout: axis = i/128 (the FREE axis), combo = (i%128)/32, pos = i%32.
    if (threadIdx.x < NEDGE) {
        int i = threadIdx.x;
        int axis  = i >> 7;
        int combo = (i >> 5) & 3;
        int pos   = i & 31;
        int hi0 = (combo >> 1) * 31;
        int hi1 = (combo & 1) * 31;
        int ix, iy, iz;
        if (axis == 0)      { ix = pos; iy = hi0; iz = hi1; }
        else if (axis == 1) { ix = hi0; iy = pos; iz = hi1; }
        else                { ix = hi0; iy = hi1; iz = pos; }
        int lin = ix * 1024 + iy * 32 + iz;
        const float* c = cpb + 3 * lin;
        s_edge[i] = make_float4(__ldg(c), __ldg(c + 1), __ldg(c + 2), __ldg(vb + lin));
    }
    // Stage symmetry params (keeps register pressure off the main loop).
    if (threadIdx.x >= NEDGE && threadIdx.x < NEDGE + S_SYM) {
        int s = threadIdx.x - NEDGE;
        s_sym[s]         = reinterpret_cast<const float4*>(planes)[s * B_BATCH + b];
        s_sym[S_SYM + s] = reinterpret_cast<const float4*>(quats)[s * B_BATCH + b];
    }
    // Stage the batch's points once (shared across all 3 symmetries).
    for (int i = threadIdx.x; i < N_PTS; i += NTHREADS)
        s_pts[i] = make_float4(pb[3 * i + 0], pb[3 * i + 1], pb[3 * i + 2], 0.0f);
    __syncthreads();

    float lp = 0.0f, lq = 0.0f;

    for (int n = threadIdx.x; n < N_PTS; n += NTHREADS) {
        float4 p = s_pts[n];
        const float px = p.x, py = p.y, pz = p.z;

        #pragma unroll
        for (int s = 0; s < S_SYM; s++) {
            float4 pl = s_sym[s];
            float4 qq = s_sym[S_SYM + s];

            // plane reflection: p' = p - 2*(p.n + d)/(|n|^2+1e-8) * n
            float t = 2.0f * (px * pl.x + py * pl.y + pz * pl.z + pl.w)
                      * fast_rcp(pl.x * pl.x + pl.y * pl.y + pl.z * pl.z + 1e-8f);
            float tx0 = px - t * pl.x;
            float ty0 = py - t * pl.y;
            float tz0 = pz - t * pl.z;

            // quat rotation (w,x,y,z) = (qq.x..qq.w), unnormalized
            float qw = qq.x, qx = qq.y, qy = qq.z, qz = qq.w;
            float tw = -qx * px - qy * py - qz * pz;
            float ax =  qw * px + qy * pz - qz * py;
            float ay =  qw * py - qx * pz + qz * px;
            float az =  qw * pz + qx * py - qy * px;
            float tx1 = -tw * qx + ax * qw - ay * qz + az * qy;
            float ty1 = -tw * qy + ax * qz + ay * qw - az * qx;
            float tz1 = -tw * qz - ax * qy + ay * qx + az * qw;

            // voxel indices + edge classification for both transforms
            int lin0, lin1, ei0, ei1;
            bool e0, e1;
            {
                float vx = fminf(fmaxf((tx0 - GRID_MIN_F) * 32.0f, 0.0f), 31.0f);
                float vy = fminf(fmaxf((ty0 - GRID_MIN_F) * 32.0f, 0.0f), 31.0f);
                float vz = fminf(fmaxf((tz0 - GRID_MIN_F) * 32.0f, 0.0f), 31.0f);
                int ix = __float2int_rn(vx), iy = __float2int_rn(vy), iz = __float2int_rn(vz);
                lin0 = ix * 1024 + iy * 32 + iz;
                bool cx = (ix * (31 - ix) == 0), cy = (iy * (31 - iy) == 0), cz = (iz * (31 - iz) == 0);
                e0 = ((int)cx + (int)cy + (int)cz) >= 2;
                if (!cx)      ei0 =       ((iy >> 4) * 2 + (iz >> 4)) * 32 + ix;
                else if (!cy) ei0 = 128 + ((ix >> 4) * 2 + (iz >> 4)) * 32 + iy;
                else          ei0 = 256 + ((ix >> 4) * 2 + (iy >> 4)) * 32 + iz;
            }
            {
                float vx = fminf(fmaxf((tx1 - GRID_MIN_F) * 32.0f, 0.0f), 31.0f);
                float vy = fminf(fmaxf((ty1 - GRID_MIN_F) * 32.0f, 0.0f), 31.0f);
                float vz = fminf(fmaxf((tz1 - GRID_MIN_F) * 32.0f, 0.0f), 31.0f);
                int ix = __float2int_rn(vx), iy = __float2int_rn(vy), iz = __float2int_rn(vz);
                lin1 = ix * 1024 + iy * 32 + iz;
                bool cx = (ix * (31 - ix) == 0), cy = (iy * (31 - iy) == 0), cz = (iz * (31 - iz) == 0);
                e1 = ((int)cx + (int)cy + (int)cz) >= 2;
                if (!cx)      ei1 =       ((iy >> 4) * 2 + (iz >> 4)) * 32 + ix;
                else if (!cy) ei1 = 128 + ((ix >> 4) * 2 + (iz >> 4)) * 32 + iy;
                else          ei1 = 256 + ((ix >> 4) * 2 + (iy >> 4)) * 32 + iz;
            }

            // Gather both voxels (batched; smem for edges, LDG otherwise).
            float vm0, c00, c01, c02, vm1, c10, c11, c12;
            if (e0) {
                float4 cc = s_edge[ei0];
                c00 = cc.x; c01 = cc.y; c02 = cc.z; vm0 = cc.w;
            } else {
                const float* c = cpb + 3 * lin0;
                vm0 = __ldg(vb + lin0);
                c00 = __ldg(c + 0); c01 = __ldg(c + 1); c02 = __ldg(c + 2);
            }
            if (e1) {
                float4 cc = s_edge[ei1];
                c10 = cc.x; c11 = cc.y; c12 = cc.z; vm1 = cc.w;
            } else {
                const float* c = cpb + 3 * lin1;
                vm1 = __ldg(vb + lin1);
                c10 = __ldg(c + 0); c11 = __ldg(c + 1); c12 = __ldg(c + 2);
            }

            float m0 = 1.0f - vm0;
            float dx = (tx0 - c00) * m0;
            float dy = (ty0 - c01) * m0;
            float dz = (tz0 - c02) * m0;
            lp += fast_sqrt(fmaxf(dx * dx + dy * dy + dz * dz, 1e-30f));

            float m1 = 1.0f - vm1;
            float ex = (tx1 - c10) * m1;
            float ey = (ty1 - c11) * m1;
            float ez = (tz1 - c12) * m1;
            lq += fast_sqrt(fmaxf(ex * ex + ey * ey + ez * ez, 1e-30f));
        }
    }

    // Deterministic block reduction: warp shuffle then fixed-order smem sum.
    #pragma unroll
    for (int off = 16; off > 0; off >>= 1) {
        lp += __shfl_down_sync(0xffffffffu, lp, off);
        lq += __shfl_down_sync(0xffffffffu, lq, off);
    }
    const int lane = threadIdx.x & 31;
    const int wid  = threadIdx.x >> 5;
    if (lane == 0) { s_red[wid] = lp; s_red[NWARPS + wid] = lq; }
    __syncthreads();
    if (threadIdx.x == 0) {
        float a = 0.0f, c2s = 0.0f;
        #pragma unroll
        for (int i = 0; i < NWARPS; i++) { a += s_red[i]; c2s += s_red[NWARPS + i]; }
        g_partial[b] = a;
        g_partial[B_BATCH + b] = c2s;
        __threadfence();
        unsigned t = atomicAdd(&g_count, 1u);
        s_is_last = (t == B_BATCH - 1);
    }
    __syncthreads();

    // Last block performs the final reduction in a FIXED order (deterministic
    // regardless of which block finishes last).
    if (s_is_last) {
        float a = 0.0f, c2s = 0.0f;
        for (int i = threadIdx.x; i < B_BATCH; i += NTHREADS) {
            a   += g_partial[i];
            c2s += g_partial[B_BATCH + i];
        }
        #pragma unroll
        for (int off = 16; off > 0; off >>= 1) {
            a   += __shfl_down_sync(0xffffffffu, a,   off);
            c2s += __shfl_down_sync(0xffffffffu, c2s, off);
        }
        if (lane == 0) { s_red[wid] = a; s_red[NWARPS + wid] = c2s; }
        __syncthreads();
        if (threadIdx.x == 0) {
            float sa = 0.0f, sc = 0.0f;
            #pragma unroll
            for (int i = 0; i < NWARPS; i++) { sa += s_red[i]; sc += s_red[NWARPS + i]; }
            out[0] = sa * (1.0f / (float)SB_TOT);
            out[1] = sc * (1.0f / (float)SB_TOT);
            g_count = 0;   // reset for next graph replay
        }
    }
}

extern "C" void kernel_launch(void* const* d_in, const int* in_sizes, int n_in,
                              void* d_out, int out_size)
{
    const float* planes = (const float*)d_in[0];  // (3,512,4)
    const float* quats  = (const float*)d_in[1];  // (3,512,4)
    const float* cps    = (const float*)d_in[2];  // (512, 32768*3)
    const float* pts    = (const float*)d_in[3];  // (512,1000,3)
    const float* vol    = (const float*)d_in[4];  // (512,1,32,32,32)
    float* out = (float*)d_out;                   // [lp_mean, lq_mean]

    sym_loss_kernel<<<B_BATCH, NTHREADS>>>(planes, quats, cps, pts, vol, out);
}

// round 10
// speedup vs baseline: 1.2850x; 1.0166x over previous
#include <cuda_runtime.h>

// Problem constants (fixed by the reference):
//   S=3 symmetries, B=512 batches, N=1000 points, G=32 (G^3=32768 voxels)
//   GRID_MIN = -0.5 + 0.5/32 = -0.484375, scale = GRID/(2*GBOUND) = 32
#define S_SYM   3
#define B_BATCH 512
#define N_PTS   1000
#define G3      32768
#define SB_TOT  (S_SYM * B_BATCH)
#define GRID_MIN_F (-0.484375f)
#define NTHREADS 512
#define NWARPS   (NTHREADS / 32)
#define NEDGE    384     // 3 axes * 4 clamp combos * 32 positions

// Per-batch partial sums: [0..511]=plane, [512..1023]=quat. Plus ticket.
__device__ float g_partial[2 * B_BATCH];
__device__ unsigned int g_count;   // zero-initialized; reset by last block

__device__ __forceinline__ float fast_sqrt(float x) {
    float r;
    asm("sqrt.approx.f32 %0, %1;" : "=f"(r) : "f"(x));
    return r;
}
__device__ __forceinline__ float fast_rcp(float x) {
    float r;
    asm("rcp.approx.f32 %0, %1;" : "=f"(r) : "f"(x));
    return r;
}

// Classify voxel for (x,y,z); returns true if edge/corner (>=2 coords clamped)
// and then *sidx = smem edge-cache index; else *glin = linear voxel index.
__device__ __forceinline__ bool classify(float x, float y, float z,
                                         int* sidx, int* glin)
{
    float vx = fminf(fmaxf((x - GRID_MIN_F) * 32.0f, 0.0f), 31.0f);
    float vy = fminf(fmaxf((y - GRID_MIN_F) * 32.0f, 0.0f), 31.0f);
    float vz = fminf(fmaxf((z - GRID_MIN_F) * 32.0f, 0.0f), 31.0f);
    int ix = __float2int_rn(vx);   // round-half-even == jnp.round after clip
    int iy = __float2int_rn(vy);
    int iz = __float2int_rn(vz);
    bool cx = (ix * (31 - ix) == 0);
    bool cy = (iy * (31 - iy) == 0);
    bool cz = (iz * (31 - iz) == 0);
    if (((int)cx + (int)cy + (int)cz) >= 2) {
        int idx;
        if (!cx)      idx =       ((iy >> 4) * 2 + (iz >> 4)) * 32 + ix;
        else if (!cy) idx = 128 + ((ix >> 4) * 2 + (iz >> 4)) * 32 + iy;
        else          idx = 256 + ((ix >> 4) * 2 + (iy >> 4)) * 32 + iz;
        *sidx = idx;
        return true;
    }
    *glin = ix * 1024 + iy * 32 + iz;
    return false;
}

__global__ __launch_bounds__(NTHREADS, 4)   // cap 32 regs -> 2048 thr/SM, ONE wave
void sym_loss_kernel(const float* __restrict__ planes,
                     const float* __restrict__ quats,
                     const float* __restrict__ cps,
                     const float* __restrict__ pts,
                     const float* __restrict__ vol,
                     float* __restrict__ out)
{
    __shared__ float4 s_pts[N_PTS];            // padded to 16B for LDS.128
    __shared__ float4 s_edge[NEDGE];           // {cp0,cp1,cp2,vol} of edge voxels
    __shared__ float4 s_sym[2 * S_SYM];        // [0..2]=planes, [3..5]=quats
    __shared__ float  s_red[2 * NWARPS];
    __shared__ int    s_is_last;

    const int b = blockIdx.x;                  // one block per batch
    const float* cpb = cps + (size_t)b * (3 * G3);
    const float* vb  = vol + (size_t)b * G3;

    // Stage the 384 edge voxels (>=2 coords clamped to 0/31).
    // Layout: axis = i/128 (the FREE axis), combo = (i%128)/32, pos = i%32.
    if (threadIdx.x < NEDGE) {
        int i = threadIdx.x;
        int axis  = i >> 7;
        int combo = (i >> 5) & 3;
        int pos   = i & 31;
        int hi0 = (combo >> 1) * 31;
        int hi1 = (combo & 1) * 31;
        int ix, iy, iz;
        if (axis == 0)      { ix = pos; iy = hi0; iz = hi1; }
        else if (axis == 1) { ix = hi0; iy = pos; iz = hi1; }
        else                { ix = hi0; iy = hi1; iz = pos; }
        int lin = ix * 1024 + iy * 32 + iz;
        const float* c = cpb + 3 * lin;
        s_edge[i] = make_float4(__ldg(c), __ldg(c + 1), __ldg(c + 2), __ldg(vb + lin));
    }
    // Stage symmetry params (keeps register pressure off the main loop).
    if (threadIdx.x >= NEDGE && threadIdx.x < NEDGE + S_SYM) {
        int s = threadIdx.x - NEDGE;
        s_sym[s]         = reinterpret_cast<const float4*>(planes)[s * B_BATCH + b];
        s_sym[S_SYM + s] = reinterpret_cast<const float4*>(quats)[s * B_BATCH + b];
    }
    // Stage the batch's points once (shared across all 3 symmetries).
    {
        const float* pb = pts + (size_t)b * (3 * N_PTS);
        for (int i = threadIdx.x; i < N_PTS; i += NTHREADS)
            s_pts[i] = make_float4(pb[3 * i + 0], pb[3 * i + 1], pb[3 * i + 2], 0.0f);
    }
    __syncthreads();

    float lp = 0.0f, lq = 0.0f;

    for (int n = threadIdx.x; n < N_PTS; n += NTHREADS) {
        float4 p = s_pts[n];
        const float px = p.x, py = p.y, pz = p.z;

        #pragma unroll
        for (int s = 0; s < S_SYM; s++) {
            float4 pl = s_sym[s];

            // plane reflection: p' = p - 2*(p.n + d)/(|n|^2+1e-8) * n
            float t = 2.0f * (px * pl.x + py * pl.y + pz * pl.z + pl.w)
                      * fast_rcp(pl.x * pl.x + pl.y * pl.y + pl.z * pl.z + 1e-8f);
            float tx0 = px - t * pl.x;
            float ty0 = py - t * pl.y;
            float tz0 = pz - t * pl.z;

            float4 qq = s_sym[S_SYM + s];
            // quat rotation (w,x,y,z) = (qq.x..qq.w), unnormalized
            float tw = -qq.y * px - qq.z * py - qq.w * pz;
            float ax =  qq.x * px + qq.z * pz - qq.w * py;
            float ay =  qq.x * py - qq.y * pz + qq.w * px;
            float az =  qq.x * pz + qq.y * py - qq.z * px;
            float tx1 = -tw * qq.y + ax * qq.x - ay * qq.w + az * qq.z;
            float ty1 = -tw * qq.z + ax * qq.w + ay * qq.x - az * qq.y;
            float tz1 = -tw * qq.w - ax * qq.z + ay * qq.y + az * qq.x;

            int si0 = 0, gl0 = 0, si1 = 0, gl1 = 0;
            bool e0 = classify(tx0, ty0, tz0, &si0, &gl0);
            bool e1 = classify(tx1, ty1, tz1, &si1, &gl1);

            // Gather both voxels (batched; smem for edges, LDG otherwise).
            float vm0, c00, c01, c02, vm1, c10, c11, c12;
            if (e0) {
                float4 cc = s_edge[si0];
                c00 = cc.x; c01 = cc.y; c02 = cc.z; vm0 = cc.w;
            } else {
                const float* c = cpb + 3 * gl0;
                vm0 = __ldg(vb + gl0);
                c00 = __ldg(c + 0); c01 = __ldg(c + 1); c02 = __ldg(c + 2);
            }
            if (e1) {
                float4 cc = s_edge[si1];
                c10 = cc.x; c11 = cc.y; c12 = cc.z; vm1 = cc.w;
            } else {
                const float* c = cpb + 3 * gl1;
                vm1 = __ldg(vb + gl1);
                c10 = __ldg(c + 0); c11 = __ldg(c + 1); c12 = __ldg(c + 2);
            }

            float m0 = 1.0f - vm0;
            float dx = (tx0 - c00) * m0;
            float dy = (ty0 - c01) * m0;
            float dz = (tz0 - c02) * m0;
            lp += fast_sqrt(fmaxf(dx * dx + dy * dy + dz * dz, 1e-30f));

            float m1 = 1.0f - vm1;
            float ex = (tx1 - c10) * m1;
            float ey = (ty1 - c11) * m1;
            float ez = (tz1 - c12) * m1;
            lq += fast_sqrt(fmaxf(ex * ex + ey * ey + ez * ez, 1e-30f));
        }
    }

    // Deterministic block reduction: warp shuffle then fixed-order smem sum.
    #pragma unroll
    for (int off = 16; off > 0; off >>= 1) {
        lp += __shfl_down_sync(0xffffffffu, lp, off);
        lq += __shfl_down_sync(0xffffffffu, lq, off);
    }
    const int lane = threadIdx.x & 31;
    const int wid  = threadIdx.x >> 5;
    if (lane == 0) { s_red[wid] = lp; s_red[NWARPS + wid] = lq; }
    __syncthreads();
    if (threadIdx.x == 0) {
        float a = 0.0f, c2s = 0.0f;
        #pragma unroll
        for (int i = 0; i < NWARPS; i++) { a += s_red[i]; c2s += s_red[NWARPS + i]; }
        g_partial[b] = a;
        g_partial[B_BATCH + b] = c2s;
        __threadfence();
        unsigned t = atomicAdd(&g_count, 1u);
        s_is_last = (t == B_BATCH - 1);
    }
    __syncthreads();

    // Last block performs the final reduction in a FIXED order (deterministic
    // regardless of which block finishes last).
    if (s_is_last) {
        float a = 0.0f, c2s = 0.0f;
        for (int i = threadIdx.x; i < B_BATCH; i += NTHREADS) {
            a   += g_partial[i];
            c2s += g_partial[B_BATCH + i];
        }
        #pragma unroll
        for (int off = 16; off > 0; off >>= 1) {
            a   += __shfl_down_sync(0xffffffffu, a,   off);
            c2s += __shfl_down_sync(0xffffffffu, c2s, off);
        }
        if (lane == 0) { s_red[wid] = a; s_red[NWARPS + wid] = c2s; }
        __syncthreads();
        if (threadIdx.x == 0) {
            float sa = 0.0f, sc = 0.0f;
            #pragma unroll
            for (int i = 0; i < NWARPS; i++) { sa += s_red[i]; sc += s_red[NWARPS + i]; }
            out[0] = sa * (1.0f / (float)SB_TOT);
            out[1] = sc * (1.0f / (float)SB_TOT);
            g_count = 0;   // reset for next graph replay
        }
    }
}

extern "C" void kernel_launch(void* const* d_in, const int* in_sizes, int n_in,
                              void* d_out, int out_size)
{
    const float* planes = (const float*)d_in[0];  // (3,512,4)
    const float* quats  = (const float*)d_in[1];  // (3,512,4)
    const float* cps    = (const float*)d_in[2];  // (512, 32768*3)
    const float* pts    = (const float*)d_in[3];  // (512,1000,3)
    const float* vol    = (const float*)d_in[4];  // (512,1,32,32,32)
    float* out = (float*)d_out;                   // [lp_mean, lq_mean]

    sym_loss_kernel<<<B_BATCH, NTHREADS>>>(planes, quats, cps, pts, vol, out);
}